// round 1
// baseline (speedup 1.0000x reference)
#include <cuda_runtime.h>
#include <math.h>

#define SEQ   4096
#define DM    1024
#define NH    16
#define DK    64
#define SSTR  65            // smem row stride (64 + 1 pad)

// ---- scratch (static device globals: allocation-free) ----
__device__ float g_q[SEQ * DM];
__device__ float g_k[SEQ * DM];
__device__ float g_v[SEQ * DM];
__device__ float g_att[SEQ * DM];
__device__ float g_rope_cos[SEQ * (DK / 2)];
__device__ float g_rope_sin[SEQ * (DK / 2)];

// ============================================================
// RoPE table: cos/sin(pos * inv_freq). Phase is rounded in fp32
// exactly like the reference (pos[f32] * inv_freq[f32]); the
// trig itself is evaluated in double so --use_fast_math cannot
// wreck argument reduction at phase ~ 4096 rad.
// ============================================================
__global__ void rope_table_kernel() {
    int t = blockIdx.x * blockDim.x + threadIdx.x;   // 4096*32 threads
    int jj  = t & 31;
    int pos = t >> 5;
    if (pos >= SEQ) return;
    float invf = (float)pow(10000.0, -(double)jj / 32.0);
    float freq = (float)pos * invf;                  // fp32 rounding (matches ref)
    g_rope_cos[pos * 32 + jj] = (float)cos((double)freq);
    g_rope_sin[pos * 32 + jj] = (float)sin((double)freq);
}

// ============================================================
// C[m,n] = sum_k A[m,k] * W[n,k]   (NT GEMM, M=4096, N=K=1024)
// BM=BN=64, BK=16, 256 threads, 4x4 register micro-tiles.
// Optional fused RoPE epilogue (rope=1 for Q and K projections).
// ============================================================
__global__ void __launch_bounds__(256) gemm_nt(const float* __restrict__ A,
                                               const float* __restrict__ W,
                                               float* __restrict__ C,
                                               int rope) {
    __shared__ float As[16][SSTR];   // [k][m]
    __shared__ float Bs[16][SSTR];   // [k][n]

    const int tid = threadIdx.x;
    const int tx  = tid & 15;
    const int ty  = tid >> 4;
    const int n0  = blockIdx.x * 64;
    const int m0  = blockIdx.y * 64;

    const int lc = tid & 15;   // k within tile (coalesced global dim)
    const int lr = tid >> 4;   // row 0..15

    float acc[4][4];
    #pragma unroll
    for (int i = 0; i < 4; i++)
        #pragma unroll
        for (int j = 0; j < 4; j++) acc[i][j] = 0.0f;

    const float* Ap = A + (size_t)(m0 + lr) * DM + lc;
    const float* Wp = W + (size_t)(n0 + lr) * DM + lc;

    for (int k0 = 0; k0 < DM; k0 += 16) {
        #pragma unroll
        for (int i = 0; i < 4; i++) {
            As[lc][lr + 16 * i] = Ap[(size_t)(i * 16) * DM + k0];
            Bs[lc][lr + 16 * i] = Wp[(size_t)(i * 16) * DM + k0];
        }
        __syncthreads();
        #pragma unroll
        for (int kk = 0; kk < 16; kk++) {
            float a[4], b[4];
            #pragma unroll
            for (int i = 0; i < 4; i++) a[i] = As[kk][ty * 4 + i];
            #pragma unroll
            for (int j = 0; j < 4; j++) b[j] = Bs[kk][tx * 4 + j];
            #pragma unroll
            for (int i = 0; i < 4; i++)
                #pragma unroll
                for (int j = 0; j < 4; j++) acc[i][j] += a[i] * b[j];
        }
        __syncthreads();
    }

    if (rope) {
        // this thread owns columns n0+4tx .. n0+4tx+3: two adjacent rope pairs
        const int d0  = (n0 + tx * 4) & (DK - 1);   // even dim within head
        const int jj0 = d0 >> 1;
        #pragma unroll
        for (int i = 0; i < 4; i++) {
            const int pos = m0 + ty * 4 + i;
            const float c0 = g_rope_cos[pos * 32 + jj0];
            const float s0 = g_rope_sin[pos * 32 + jj0];
            const float c1 = g_rope_cos[pos * 32 + jj0 + 1];
            const float s1 = g_rope_sin[pos * 32 + jj0 + 1];
            float e = acc[i][0], o = acc[i][1];
            acc[i][0] = c0 * e - s0 * o;
            acc[i][1] = s0 * e + c0 * o;
            e = acc[i][2]; o = acc[i][3];
            acc[i][2] = c1 * e - s1 * o;
            acc[i][3] = s1 * e + c1 * o;
        }
    }

    #pragma unroll
    for (int i = 0; i < 4; i++) {
        float4 v = make_float4(acc[i][0], acc[i][1], acc[i][2], acc[i][3]);
        *(float4*)&C[(size_t)(m0 + ty * 4 + i) * DM + n0 + tx * 4] = v;
    }
}

// ============================================================
// Causal flash attention. One CTA = (head, 64-query block).
// Online softmax; 64x64 K/V tiles streamed through smem.
// ============================================================
__global__ void __launch_bounds__(256) attn_kernel() {
    extern __shared__ float sm[];
    float (*Qs)[SSTR] = (float(*)[SSTR])(sm);
    float (*Ks)[SSTR] = (float(*)[SSTR])(sm + 1 * 64 * SSTR);
    float (*Vs)[SSTR] = (float(*)[SSTR])(sm + 2 * 64 * SSTR);
    float (*Ps)[SSTR] = (float(*)[SSTR])(sm + 3 * 64 * SSTR);

    const int tid = threadIdx.x;
    const int tx  = tid & 15;
    const int ty  = tid >> 4;
    const int h   = blockIdx.y;
    const int qb  = gridDim.x - 1 - blockIdx.x;   // heavy blocks first
    const int q0  = qb * 64;
    const int hc  = h * DK;

    // load Q tile (float4 coalesced)
    {
        const int c4 = tid & 15, r = tid >> 4;
        #pragma unroll
        for (int i = 0; i < 4; i++) {
            float4 v = *(const float4*)&g_q[(size_t)(q0 + r + 16 * i) * DM + hc + c4 * 4];
            float* dst = &Qs[r + 16 * i][c4 * 4];
            dst[0] = v.x; dst[1] = v.y; dst[2] = v.z; dst[3] = v.w;
        }
    }

    float acc[4][4];
    float m_i[4], l_i[4];
    #pragma unroll
    for (int i = 0; i < 4; i++) {
        m_i[i] = -1e30f; l_i[i] = 0.0f;
        #pragma unroll
        for (int j = 0; j < 4; j++) acc[i][j] = 0.0f;
    }

    for (int kb = 0; kb <= qb; kb++) {
        const int k0 = kb * 64;
        if (kb) __syncthreads();   // PV readers done before overwrite
        // load K, V tiles
        {
            const int c4 = tid & 15, r = tid >> 4;
            #pragma unroll
            for (int i = 0; i < 4; i++) {
                const size_t off = (size_t)(k0 + r + 16 * i) * DM + hc + c4 * 4;
                float4 kv = *(const float4*)&g_k[off];
                float* kd = &Ks[r + 16 * i][c4 * 4];
                kd[0] = kv.x; kd[1] = kv.y; kd[2] = kv.z; kd[3] = kv.w;
                float4 vv = *(const float4*)&g_v[off];
                float* vd = &Vs[r + 16 * i][c4 * 4];
                vd[0] = vv.x; vd[1] = vv.y; vd[2] = vv.z; vd[3] = vv.w;
            }
        }
        __syncthreads();

        // S = Q K^T / 8
        float s[4][4];
        #pragma unroll
        for (int i = 0; i < 4; i++)
            #pragma unroll
            for (int j = 0; j < 4; j++) s[i][j] = 0.0f;

        #pragma unroll 8
        for (int d = 0; d < DK; d++) {
            float a[4], b[4];
            #pragma unroll
            for (int i = 0; i < 4; i++) a[i] = Qs[ty * 4 + i][d];
            #pragma unroll
            for (int j = 0; j < 4; j++) b[j] = Ks[tx * 4 + j][d];
            #pragma unroll
            for (int i = 0; i < 4; i++)
                #pragma unroll
                for (int j = 0; j < 4; j++) s[i][j] += a[i] * b[j];
        }

        const bool diag = (kb == qb);
        #pragma unroll
        for (int i = 0; i < 4; i++)
            #pragma unroll
            for (int j = 0; j < 4; j++) {
                s[i][j] *= 0.125f;
                if (diag && (k0 + tx * 4 + j > q0 + ty * 4 + i)) s[i][j] = -1e30f;
            }

        // online softmax (row reductions across the 16 tx lanes)
        #pragma unroll
        for (int i = 0; i < 4; i++) {
            float mx = fmaxf(fmaxf(s[i][0], s[i][1]), fmaxf(s[i][2], s[i][3]));
            #pragma unroll
            for (int off = 8; off; off >>= 1)
                mx = fmaxf(mx, __shfl_xor_sync(0xffffffffu, mx, off, 16));
            const float mnew = fmaxf(m_i[i], mx);
            float p0 = expf(s[i][0] - mnew);
            float p1 = expf(s[i][1] - mnew);
            float p2 = expf(s[i][2] - mnew);
            float p3 = expf(s[i][3] - mnew);
            float sum = (p0 + p1) + (p2 + p3);
            #pragma unroll
            for (int off = 8; off; off >>= 1)
                sum += __shfl_xor_sync(0xffffffffu, sum, off, 16);
            const float alpha = expf(m_i[i] - mnew);
            l_i[i] = l_i[i] * alpha + sum;
            m_i[i] = mnew;
            #pragma unroll
            for (int j = 0; j < 4; j++) acc[i][j] *= alpha;
            float* pr = &Ps[ty * 4 + i][tx * 4];
            pr[0] = p0; pr[1] = p1; pr[2] = p2; pr[3] = p3;
        }
        __syncthreads();

        // O += P V
        #pragma unroll 8
        for (int c = 0; c < 64; c++) {
            float a[4], b[4];
            #pragma unroll
            for (int i = 0; i < 4; i++) a[i] = Ps[ty * 4 + i][c];
            #pragma unroll
            for (int j = 0; j < 4; j++) b[j] = Vs[c][tx * 4 + j];
            #pragma unroll
            for (int i = 0; i < 4; i++)
                #pragma unroll
                for (int j = 0; j < 4; j++) acc[i][j] += a[i] * b[j];
        }
    }

    // normalize + write
    #pragma unroll
    for (int i = 0; i < 4; i++) {
        const float inv = 1.0f / l_i[i];
        float4 v = make_float4(acc[i][0] * inv, acc[i][1] * inv,
                               acc[i][2] * inv, acc[i][3] * inv);
        *(float4*)&g_att[(size_t)(q0 + ty * 4 + i) * DM + hc + tx * 4] = v;
    }
}

// ============================================================
// launch
// ============================================================
extern "C" void kernel_launch(void* const* d_in, const int* in_sizes, int n_in,
                              void* d_out, int out_size) {
    const float* x  = (const float*)d_in[0];
    const float* wq = (const float*)d_in[1];
    const float* wk = (const float*)d_in[2];
    const float* wv = (const float*)d_in[3];
    const float* wo = (const float*)d_in[4];
    float* out = (float*)d_out;

    float *qp, *kp, *vp, *ap;
    cudaGetSymbolAddress((void**)&qp, g_q);
    cudaGetSymbolAddress((void**)&kp, g_k);
    cudaGetSymbolAddress((void**)&vp, g_v);
    cudaGetSymbolAddress((void**)&ap, g_att);

    const int attn_smem = 4 * 64 * SSTR * (int)sizeof(float);   // 66560 B
    cudaFuncSetAttribute(attn_kernel,
                         cudaFuncAttributeMaxDynamicSharedMemorySize, attn_smem);

    rope_table_kernel<<<(SEQ * 32) / 256, 256>>>();

    dim3 gg(DM / 64, SEQ / 64);
    gemm_nt<<<gg, 256>>>(x, wq, qp, 1);
    gemm_nt<<<gg, 256>>>(x, wk, kp, 1);
    gemm_nt<<<gg, 256>>>(x, wv, vp, 0);

    attn_kernel<<<dim3(SEQ / 64, NH), 256, attn_smem>>>();

    gemm_nt<<<gg, 256>>>(ap, wo, out, 0);
}

// round 3
// speedup vs baseline: 1.6374x; 1.6374x over previous
#include <cuda_runtime.h>
#include <cuda_bf16.h>
#include <math.h>
#include <cstdint>

#define SEQ   4096
#define DM    1024
#define NH    16
#define DK    64
#define SSTR  65            // smem row stride for attn (64 + 1 pad)

// ---- fp32 intermediates ----
__device__ float g_q[SEQ * DM];
__device__ float g_k[SEQ * DM];
__device__ float g_v[SEQ * DM];
__device__ float g_att[SEQ * DM];
__device__ float g_rope_cos[SEQ * 32];
__device__ float g_rope_sin[SEQ * 32];

// ---- bf16 hi/lo split buffers ----
__device__ __nv_bfloat16 g_xh[SEQ * DM], g_xl[SEQ * DM];
__device__ __nv_bfloat16 g_ah[SEQ * DM], g_al[SEQ * DM];
__device__ __nv_bfloat16 g_wqh[DM * DM], g_wql[DM * DM];
__device__ __nv_bfloat16 g_wkh[DM * DM], g_wkl[DM * DM];
__device__ __nv_bfloat16 g_wvh[DM * DM], g_wvl[DM * DM];
__device__ __nv_bfloat16 g_woh[DM * DM], g_wol[DM * DM];

// ============================================================
// RoPE table (double trig, fp32 phase rounding like the reference)
// ============================================================
__global__ void rope_table_kernel() {
    int t = blockIdx.x * blockDim.x + threadIdx.x;
    int jj  = t & 31;
    int pos = t >> 5;
    if (pos >= SEQ) return;
    float invf = (float)pow(10000.0, -(double)jj / 32.0);
    float freq = (float)pos * invf;
    g_rope_cos[pos * 32 + jj] = (float)cos((double)freq);
    g_rope_sin[pos * 32 + jj] = (float)sin((double)freq);
}

// ============================================================
// fp32 -> (hi, lo) bf16 split
// ============================================================
__global__ void conv_split(const float4* __restrict__ src,
                           __nv_bfloat162* __restrict__ hi,
                           __nv_bfloat162* __restrict__ lo, int n4) {
    int i = blockIdx.x * blockDim.x + threadIdx.x;
    if (i >= n4) return;
    float4 v = src[i];
    __nv_bfloat16 h0 = __float2bfloat16(v.x);
    __nv_bfloat16 h1 = __float2bfloat16(v.y);
    __nv_bfloat16 h2 = __float2bfloat16(v.z);
    __nv_bfloat16 h3 = __float2bfloat16(v.w);
    __nv_bfloat162 a, b, c, d;
    a.x = h0; a.y = h1;
    b.x = h2; b.y = h3;
    c.x = __float2bfloat16(v.x - __bfloat162float(h0));
    c.y = __float2bfloat16(v.y - __bfloat162float(h1));
    d.x = __float2bfloat16(v.z - __bfloat162float(h2));
    d.y = __float2bfloat16(v.w - __bfloat162float(h3));
    hi[2 * i + 0] = a;
    hi[2 * i + 1] = b;
    lo[2 * i + 0] = c;
    lo[2 * i + 1] = d;
}

// ============================================================
// warp-mma helpers (sm_80-era, legal on plain sm_103)
// ============================================================
__device__ __forceinline__ uint32_t s2u(const void* p) {
    uint32_t a;
    asm("{ .reg .u64 t; cvta.to.shared.u64 t, %1; cvt.u32.u64 %0, t; }"
        : "=r"(a) : "l"(p));
    return a;
}

__device__ __forceinline__ void mma16816(float* d, const uint32_t* a,
                                         const uint32_t* b) {
    asm volatile(
        "mma.sync.aligned.m16n8k16.row.col.f32.bf16.bf16.f32 "
        "{%0,%1,%2,%3}, {%4,%5,%6,%7}, {%8,%9}, {%0,%1,%2,%3};"
        : "+f"(d[0]), "+f"(d[1]), "+f"(d[2]), "+f"(d[3])
        : "r"(a[0]), "r"(a[1]), "r"(a[2]), "r"(a[3]), "r"(b[0]), "r"(b[1]));
}

__device__ __forceinline__ void ldsm4(uint32_t* r, uint32_t addr) {
    asm volatile("ldmatrix.sync.aligned.m8n8.x4.shared.b16 {%0,%1,%2,%3}, [%4];"
                 : "=r"(r[0]), "=r"(r[1]), "=r"(r[2]), "=r"(r[3]) : "r"(addr));
}

__device__ __forceinline__ void ldsm2(uint32_t* r, uint32_t addr) {
    asm volatile("ldmatrix.sync.aligned.m8n8.x2.shared.b16 {%0,%1}, [%2];"
                 : "=r"(r[0]), "=r"(r[1]) : "r"(addr));
}

// ============================================================
// bf16x3 GEMM via mma.sync:  D[m,n] = sum_k A[m,k] * B[n,k]
// CTA 128x128, BK=32, 256 thr (8 warps, 64x32 warp tiles),
// cp.async double buffer, smem rows padded to 40 bf16.
// blockIdx.x: N-tiles 0-7 -> B0/D0, 8-15 -> B1/D1, 16-23 -> B2/D2.
// ============================================================
#define KPAD      40
#define TILE_B    (128 * KPAD * 2)      // 10240 B per 128x32 bf16 tile
#define STAGE_B   (4 * TILE_B)          // Ah, Al, Bh, Bl
#define GEMM_SMEM (2 * STAGE_B)         // 81920 B

__device__ __forceinline__ void load_tile4(uint32_t st,
                                           const __nv_bfloat16* ah,
                                           const __nv_bfloat16* al,
                                           const __nv_bfloat16* bh,
                                           const __nv_bfloat16* bl, int tid) {
    #pragma unroll
    for (int i = 0; i < 2; i++) {
        int c   = tid + 256 * i;
        int row = c >> 2;
        int sg  = (c & 3) << 4;          // byte offset of 16B segment
        uint32_t soff = (uint32_t)row * (KPAD * 2) + (uint32_t)sg;
        size_t   goff = (size_t)row * (DM * 2) + sg;
        asm volatile("cp.async.cg.shared.global [%0], [%1], 16;"
                     :: "r"(st + 0 * TILE_B + soff), "l"((const char*)ah + goff) : "memory");
        asm volatile("cp.async.cg.shared.global [%0], [%1], 16;"
                     :: "r"(st + 1 * TILE_B + soff), "l"((const char*)al + goff) : "memory");
        asm volatile("cp.async.cg.shared.global [%0], [%1], 16;"
                     :: "r"(st + 2 * TILE_B + soff), "l"((const char*)bh + goff) : "memory");
        asm volatile("cp.async.cg.shared.global [%0], [%1], 16;"
                     :: "r"(st + 3 * TILE_B + soff), "l"((const char*)bl + goff) : "memory");
    }
}

__global__ void __launch_bounds__(256)
gemm_tc(const __nv_bfloat16* __restrict__ Ah, const __nv_bfloat16* __restrict__ Al,
        const __nv_bfloat16* __restrict__ B0h, const __nv_bfloat16* __restrict__ B0l,
        const __nv_bfloat16* __restrict__ B1h, const __nv_bfloat16* __restrict__ B1l,
        const __nv_bfloat16* __restrict__ B2h, const __nv_bfloat16* __restrict__ B2l,
        float* __restrict__ D0, float* __restrict__ D1, float* __restrict__ D2,
        int do_rope) {
    extern __shared__ char smraw[];
    const uint32_t sb = s2u(smraw);

    const int tid  = threadIdx.x;
    const int lane = tid & 31;
    const int wid  = tid >> 5;
    const int warp_m = (wid & 1) * 64;   // 2 warps in M
    const int warp_n = (wid >> 1) * 32;  // 4 warps in N

    const int ntile = blockIdx.x;
    const int which = ntile >> 3;
    const int nloc  = (ntile & 7) * 128;
    const int m0    = blockIdx.y * 128;

    const __nv_bfloat16* Bh = (which == 0) ? B0h : (which == 1) ? B1h : B2h;
    const __nv_bfloat16* Bl = (which == 0) ? B0l : (which == 1) ? B1l : B2l;
    float* Dst              = (which == 0) ? D0  : (which == 1) ? D1  : D2;
    const int rope = do_rope && (which < 2);

    const __nv_bfloat16* Abh = Ah + (size_t)m0 * DM;
    const __nv_bfloat16* Abl = Al + (size_t)m0 * DM;
    const __nv_bfloat16* Bbh = Bh + (size_t)nloc * DM;
    const __nv_bfloat16* Bbl = Bl + (size_t)nloc * DM;

    float acc[4][4][4];
    #pragma unroll
    for (int i = 0; i < 4; i++)
        #pragma unroll
        for (int j = 0; j < 4; j++)
            #pragma unroll
            for (int r = 0; r < 4; r++) acc[i][j][r] = 0.0f;

    // precomputed ldmatrix lane addresses (byte offsets within a tile)
    const uint32_t a_off = (uint32_t)(lane & 15) * (KPAD * 2) + (uint32_t)(lane >> 4) * 16;
    const int bl16 = lane & 15;
    const uint32_t b_off = (uint32_t)(bl16 & 7) * (KPAD * 2) + (uint32_t)(bl16 >> 3) * 16;

    load_tile4(sb, Abh, Abl, Bbh, Bbl, tid);
    asm volatile("cp.async.commit_group;" ::: "memory");

    for (int kb = 0; kb < 32; kb++) {
        const uint32_t st = sb + (uint32_t)(kb & 1) * STAGE_B;
        if (kb + 1 < 32) {
            const int ko = (kb + 1) * 32;
            load_tile4(sb + (uint32_t)((kb + 1) & 1) * STAGE_B,
                       Abh + ko, Abl + ko, Bbh + ko, Bbl + ko, tid);
            asm volatile("cp.async.commit_group;" ::: "memory");
            asm volatile("cp.async.wait_group 1;" ::: "memory");
        } else {
            asm volatile("cp.async.wait_group 0;" ::: "memory");
        }
        __syncthreads();

        #pragma unroll
        for (int ks = 0; ks < 2; ks++) {
            const uint32_t k0b = (uint32_t)ks * 32;   // 16 bf16 = 32 B
            uint32_t ahf[4][4], alf[4][4], bhf[4][2], blf[4][2];
            #pragma unroll
            for (int mi = 0; mi < 4; mi++) {
                uint32_t ra = (uint32_t)(warp_m + mi * 16) * (KPAD * 2) + k0b + a_off;
                ldsm4(ahf[mi], st + 0 * TILE_B + ra);
                ldsm4(alf[mi], st + 1 * TILE_B + ra);
            }
            #pragma unroll
            for (int ni = 0; ni < 4; ni++) {
                uint32_t rb = (uint32_t)(warp_n + ni * 8) * (KPAD * 2) + k0b + b_off;
                ldsm2(bhf[ni], st + 2 * TILE_B + rb);
                ldsm2(blf[ni], st + 3 * TILE_B + rb);
            }
            #pragma unroll
            for (int mi = 0; mi < 4; mi++)
                #pragma unroll
                for (int ni = 0; ni < 4; ni++) {
                    mma16816(acc[mi][ni], ahf[mi], bhf[ni]);
                    mma16816(acc[mi][ni], ahf[mi], blf[ni]);
                    mma16816(acc[mi][ni], alf[mi], bhf[ni]);
                }
        }
        __syncthreads();
    }

    // epilogue: fragment row = warp_m + mi*16 + lane/4 (+8), col = warp_n + ni*8 + (lane%4)*2
    #pragma unroll
    for (int mi = 0; mi < 4; mi++) {
        #pragma unroll
        for (int ni = 0; ni < 4; ni++) {
            const int r0  = m0 + warp_m + mi * 16 + (lane >> 2);
            const int cl  = warp_n + ni * 8 + (lane & 3) * 2;   // col within 128-tile
            const int col = nloc + cl;
            float c0 = acc[mi][ni][0], c1 = acc[mi][ni][1];
            float c2 = acc[mi][ni][2], c3 = acc[mi][ni][3];
            if (rope) {
                const int jj = (col & (DK - 1)) >> 1;
                float cs = g_rope_cos[r0 * 32 + jj];
                float sn = g_rope_sin[r0 * 32 + jj];
                float e = c0, o = c1;
                c0 = cs * e - sn * o;
                c1 = sn * e + cs * o;
                cs = g_rope_cos[(r0 + 8) * 32 + jj];
                sn = g_rope_sin[(r0 + 8) * 32 + jj];
                e = c2; o = c3;
                c2 = cs * e - sn * o;
                c3 = sn * e + cs * o;
            }
            *(float2*)&Dst[(size_t)r0 * DM + col]       = make_float2(c0, c1);
            *(float2*)&Dst[(size_t)(r0 + 8) * DM + col] = make_float2(c2, c3);
        }
    }
}

// ============================================================
// Causal flash attention (unchanged — fp32, 64x64 tiles)
// ============================================================
__global__ void __launch_bounds__(256) attn_kernel() {
    extern __shared__ float sm[];
    float (*Qs)[SSTR] = (float(*)[SSTR])(sm);
    float (*Ks)[SSTR] = (float(*)[SSTR])(sm + 1 * 64 * SSTR);
    float (*Vs)[SSTR] = (float(*)[SSTR])(sm + 2 * 64 * SSTR);
    float (*Ps)[SSTR] = (float(*)[SSTR])(sm + 3 * 64 * SSTR);

    const int tid = threadIdx.x;
    const int tx  = tid & 15;
    const int ty  = tid >> 4;
    const int h   = blockIdx.y;
    const int qb  = gridDim.x - 1 - blockIdx.x;
    const int q0  = qb * 64;
    const int hc  = h * DK;

    {
        const int c4 = tid & 15, r = tid >> 4;
        #pragma unroll
        for (int i = 0; i < 4; i++) {
            float4 v = *(const float4*)&g_q[(size_t)(q0 + r + 16 * i) * DM + hc + c4 * 4];
            float* dst = &Qs[r + 16 * i][c4 * 4];
            dst[0] = v.x; dst[1] = v.y; dst[2] = v.z; dst[3] = v.w;
        }
    }

    float acc[4][4];
    float m_i[4], l_i[4];
    #pragma unroll
    for (int i = 0; i < 4; i++) {
        m_i[i] = -1e30f; l_i[i] = 0.0f;
        #pragma unroll
        for (int j = 0; j < 4; j++) acc[i][j] = 0.0f;
    }

    for (int kb = 0; kb <= qb; kb++) {
        const int k0 = kb * 64;
        if (kb) __syncthreads();
        {
            const int c4 = tid & 15, r = tid >> 4;
            #pragma unroll
            for (int i = 0; i < 4; i++) {
                const size_t off = (size_t)(k0 + r + 16 * i) * DM + hc + c4 * 4;
                float4 kv = *(const float4*)&g_k[off];
                float* kd = &Ks[r + 16 * i][c4 * 4];
                kd[0] = kv.x; kd[1] = kv.y; kd[2] = kv.z; kd[3] = kv.w;
                float4 vv = *(const float4*)&g_v[off];
                float* vd = &Vs[r + 16 * i][c4 * 4];
                vd[0] = vv.x; vd[1] = vv.y; vd[2] = vv.z; vd[3] = vv.w;
            }
        }
        __syncthreads();

        float s[4][4];
        #pragma unroll
        for (int i = 0; i < 4; i++)
            #pragma unroll
            for (int j = 0; j < 4; j++) s[i][j] = 0.0f;

        #pragma unroll 8
        for (int d = 0; d < DK; d++) {
            float a[4], b[4];
            #pragma unroll
            for (int i = 0; i < 4; i++) a[i] = Qs[ty * 4 + i][d];
            #pragma unroll
            for (int j = 0; j < 4; j++) b[j] = Ks[tx * 4 + j][d];
            #pragma unroll
            for (int i = 0; i < 4; i++)
                #pragma unroll
                for (int j = 0; j < 4; j++) s[i][j] += a[i] * b[j];
        }

        const bool diag = (kb == qb);
        #pragma unroll
        for (int i = 0; i < 4; i++)
            #pragma unroll
            for (int j = 0; j < 4; j++) {
                s[i][j] *= 0.125f;
                if (diag && (k0 + tx * 4 + j > q0 + ty * 4 + i)) s[i][j] = -1e30f;
            }

        #pragma unroll
        for (int i = 0; i < 4; i++) {
            float mx = fmaxf(fmaxf(s[i][0], s[i][1]), fmaxf(s[i][2], s[i][3]));
            #pragma unroll
            for (int off = 8; off; off >>= 1)
                mx = fmaxf(mx, __shfl_xor_sync(0xffffffffu, mx, off, 16));
            const float mnew = fmaxf(m_i[i], mx);
            float p0 = expf(s[i][0] - mnew);
            float p1 = expf(s[i][1] - mnew);
            float p2 = expf(s[i][2] - mnew);
            float p3 = expf(s[i][3] - mnew);
            float sum = (p0 + p1) + (p2 + p3);
            #pragma unroll
            for (int off = 8; off; off >>= 1)
                sum += __shfl_xor_sync(0xffffffffu, sum, off, 16);
            const float alpha = expf(m_i[i] - mnew);
            l_i[i] = l_i[i] * alpha + sum;
            m_i[i] = mnew;
            #pragma unroll
            for (int j = 0; j < 4; j++) acc[i][j] *= alpha;
            float* pr = &Ps[ty * 4 + i][tx * 4];
            pr[0] = p0; pr[1] = p1; pr[2] = p2; pr[3] = p3;
        }
        __syncthreads();

        #pragma unroll 8
        for (int c = 0; c < 64; c++) {
            float a[4], b[4];
            #pragma unroll
            for (int i = 0; i < 4; i++) a[i] = Ps[ty * 4 + i][c];
            #pragma unroll
            for (int j = 0; j < 4; j++) b[j] = Vs[c][tx * 4 + j];
            #pragma unroll
            for (int i = 0; i < 4; i++)
                #pragma unroll
                for (int j = 0; j < 4; j++) acc[i][j] += a[i] * b[j];
        }
    }

    #pragma unroll
    for (int i = 0; i < 4; i++) {
        const float inv = 1.0f / l_i[i];
        float4 v = make_float4(acc[i][0] * inv, acc[i][1] * inv,
                               acc[i][2] * inv, acc[i][3] * inv);
        *(float4*)&g_att[(size_t)(q0 + ty * 4 + i) * DM + hc + tx * 4] = v;
    }
}

// ============================================================
// launch
// ============================================================
extern "C" void kernel_launch(void* const* d_in, const int* in_sizes, int n_in,
                              void* d_out, int out_size) {
    const float* x  = (const float*)d_in[0];
    const float* wq = (const float*)d_in[1];
    const float* wk = (const float*)d_in[2];
    const float* wv = (const float*)d_in[3];
    const float* wo = (const float*)d_in[4];
    float* out = (float*)d_out;

    float *qp, *kp, *vp, *ap;
    cudaGetSymbolAddress((void**)&qp, g_q);
    cudaGetSymbolAddress((void**)&kp, g_k);
    cudaGetSymbolAddress((void**)&vp, g_v);
    cudaGetSymbolAddress((void**)&ap, g_att);

    __nv_bfloat16 *xh, *xl, *ah, *al;
    __nv_bfloat16 *wqh, *wql, *wkh, *wkl, *wvh, *wvl, *woh, *wol;
    cudaGetSymbolAddress((void**)&xh,  g_xh);
    cudaGetSymbolAddress((void**)&xl,  g_xl);
    cudaGetSymbolAddress((void**)&ah,  g_ah);
    cudaGetSymbolAddress((void**)&al,  g_al);
    cudaGetSymbolAddress((void**)&wqh, g_wqh);
    cudaGetSymbolAddress((void**)&wql, g_wql);
    cudaGetSymbolAddress((void**)&wkh, g_wkh);
    cudaGetSymbolAddress((void**)&wkl, g_wkl);
    cudaGetSymbolAddress((void**)&wvh, g_wvh);
    cudaGetSymbolAddress((void**)&wvl, g_wvl);
    cudaGetSymbolAddress((void**)&woh, g_woh);
    cudaGetSymbolAddress((void**)&wol, g_wol);

    const int attn_smem = 4 * 64 * SSTR * (int)sizeof(float);
    cudaFuncSetAttribute(attn_kernel,
                         cudaFuncAttributeMaxDynamicSharedMemorySize, attn_smem);
    cudaFuncSetAttribute(gemm_tc,
                         cudaFuncAttributeMaxDynamicSharedMemorySize, GEMM_SMEM);

    rope_table_kernel<<<(SEQ * 32) / 256, 256>>>();

    const int nx4 = SEQ * DM / 4;
    const int nw4 = DM * DM / 4;
    conv_split<<<(nx4 + 255) / 256, 256>>>((const float4*)x,
                                           (__nv_bfloat162*)xh, (__nv_bfloat162*)xl, nx4);
    conv_split<<<(nw4 + 255) / 256, 256>>>((const float4*)wq,
                                           (__nv_bfloat162*)wqh, (__nv_bfloat162*)wql, nw4);
    conv_split<<<(nw4 + 255) / 256, 256>>>((const float4*)wk,
                                           (__nv_bfloat162*)wkh, (__nv_bfloat162*)wkl, nw4);
    conv_split<<<(nw4 + 255) / 256, 256>>>((const float4*)wv,
                                           (__nv_bfloat162*)wvh, (__nv_bfloat162*)wvl, nw4);
    conv_split<<<(nw4 + 255) / 256, 256>>>((const float4*)wo,
                                           (__nv_bfloat162*)woh, (__nv_bfloat162*)wol, nw4);

    gemm_tc<<<dim3(24, 32), 256, GEMM_SMEM>>>(xh, xl,
                                              wqh, wql, wkh, wkl, wvh, wvl,
                                              qp, kp, vp, 1);

    attn_kernel<<<dim3(SEQ / 64, NH), 256, attn_smem>>>();

    conv_split<<<(nx4 + 255) / 256, 256>>>((const float4*)ap,
                                           (__nv_bfloat162*)ah, (__nv_bfloat162*)al, nx4);

    gemm_tc<<<dim3(8, 32), 256, GEMM_SMEM>>>(ah, al,
                                             woh, wol, woh, wol, woh, wol,
                                             out, out, out, 0);
}

// round 4
// speedup vs baseline: 3.7208x; 2.2724x over previous
#include <cuda_runtime.h>
#include <cuda_bf16.h>
#include <math.h>
#include <cstdint>

#define SEQ   4096
#define DM    1024
#define NH    16
#define DK    64

// ---- bf16 hi/lo buffers ----
__device__ __nv_bfloat16 g_xh[SEQ * DM], g_xl[SEQ * DM];
__device__ __nv_bfloat16 g_ah[SEQ * DM], g_al[SEQ * DM];   // attention output
__device__ __nv_bfloat16 g_wqh[DM * DM], g_wql[DM * DM];
__device__ __nv_bfloat16 g_wkh[DM * DM], g_wkl[DM * DM];
__device__ __nv_bfloat16 g_wvh[DM * DM], g_wvl[DM * DM];
__device__ __nv_bfloat16 g_woh[DM * DM], g_wol[DM * DM];
// head-major [NH][SEQ][DK] Q/K/V hi/lo
__device__ __nv_bfloat16 g_qh[NH * SEQ * DK], g_ql[NH * SEQ * DK];
__device__ __nv_bfloat16 g_kh[NH * SEQ * DK], g_kl[NH * SEQ * DK];
__device__ __nv_bfloat16 g_vh[NH * SEQ * DK], g_vl[NH * SEQ * DK];

__device__ float g_rope_cos[SEQ * 32];
__device__ float g_rope_sin[SEQ * 32];

// ============================================================
// RoPE table (double trig, fp32 phase rounding like the reference)
// ============================================================
__global__ void rope_table_kernel() {
    int t = blockIdx.x * blockDim.x + threadIdx.x;
    int jj  = t & 31;
    int pos = t >> 5;
    if (pos >= SEQ) return;
    float invf = (float)pow(10000.0, -(double)jj / 32.0);
    float freq = (float)pos * invf;
    g_rope_cos[pos * 32 + jj] = (float)cos((double)freq);
    g_rope_sin[pos * 32 + jj] = (float)sin((double)freq);
}

// ============================================================
// fp32 -> (hi, lo) bf16 split
// ============================================================
__global__ void conv_split(const float4* __restrict__ src,
                           __nv_bfloat162* __restrict__ hi,
                           __nv_bfloat162* __restrict__ lo, int n4) {
    int i = blockIdx.x * blockDim.x + threadIdx.x;
    if (i >= n4) return;
    float4 v = src[i];
    __nv_bfloat16 h0 = __float2bfloat16(v.x);
    __nv_bfloat16 h1 = __float2bfloat16(v.y);
    __nv_bfloat16 h2 = __float2bfloat16(v.z);
    __nv_bfloat16 h3 = __float2bfloat16(v.w);
    __nv_bfloat162 a, b, c, d;
    a.x = h0; a.y = h1;
    b.x = h2; b.y = h3;
    c.x = __float2bfloat16(v.x - __bfloat162float(h0));
    c.y = __float2bfloat16(v.y - __bfloat162float(h1));
    d.x = __float2bfloat16(v.z - __bfloat162float(h2));
    d.y = __float2bfloat16(v.w - __bfloat162float(h3));
    hi[2 * i + 0] = a;
    hi[2 * i + 1] = b;
    lo[2 * i + 0] = c;
    lo[2 * i + 1] = d;
}

// ============================================================
// warp-mma helpers
// ============================================================
__device__ __forceinline__ uint32_t s2u(const void* p) {
    uint32_t a;
    asm("{ .reg .u64 t; cvta.to.shared.u64 t, %1; cvt.u32.u64 %0, t; }"
        : "=r"(a) : "l"(p));
    return a;
}

__device__ __forceinline__ void mma16816(float* d, const uint32_t* a,
                                         const uint32_t* b) {
    asm volatile(
        "mma.sync.aligned.m16n8k16.row.col.f32.bf16.bf16.f32 "
        "{%0,%1,%2,%3}, {%4,%5,%6,%7}, {%8,%9}, {%0,%1,%2,%3};"
        : "+f"(d[0]), "+f"(d[1]), "+f"(d[2]), "+f"(d[3])
        : "r"(a[0]), "r"(a[1]), "r"(a[2]), "r"(a[3]), "r"(b[0]), "r"(b[1]));
}

__device__ __forceinline__ void ldsm4(uint32_t* r, uint32_t addr) {
    asm volatile("ldmatrix.sync.aligned.m8n8.x4.shared.b16 {%0,%1,%2,%3}, [%4];"
                 : "=r"(r[0]), "=r"(r[1]), "=r"(r[2]), "=r"(r[3]) : "r"(addr));
}

__device__ __forceinline__ void ldsm4t(uint32_t* r, uint32_t addr) {
    asm volatile("ldmatrix.sync.aligned.m8n8.x4.trans.shared.b16 {%0,%1,%2,%3}, [%4];"
                 : "=r"(r[0]), "=r"(r[1]), "=r"(r[2]), "=r"(r[3]) : "r"(addr));
}

__device__ __forceinline__ void ldsm2(uint32_t* r, uint32_t addr) {
    asm volatile("ldmatrix.sync.aligned.m8n8.x2.shared.b16 {%0,%1}, [%2];"
                 : "=r"(r[0]), "=r"(r[1]) : "r"(addr));
}

__device__ __forceinline__ uint32_t packbf2(float lo, float hi) {
    __nv_bfloat162 b = __float22bfloat162_rn(make_float2(lo, hi));
    return *(uint32_t*)&b;
}

// ============================================================
// bf16x3 GEMM via mma.sync:  D[m,n] = sum_k A[m,k] * B[n,k]
// CTA 128x128, BK=32, 256 thr (8 warps, 64x32 warp tiles).
// mode 0: fp32 output to Dout.
// mode 1: QKV — RoPE (for which<2) + bf16 hi/lo split, head-major layout.
// ============================================================
#define KPAD      40
#define TILE_B    (128 * KPAD * 2)
#define STAGE_B   (4 * TILE_B)
#define GEMM_SMEM (2 * STAGE_B)

__device__ __forceinline__ void load_tile4(uint32_t st,
                                           const __nv_bfloat16* ah,
                                           const __nv_bfloat16* al,
                                           const __nv_bfloat16* bh,
                                           const __nv_bfloat16* bl, int tid) {
    #pragma unroll
    for (int i = 0; i < 2; i++) {
        int c   = tid + 256 * i;
        int row = c >> 2;
        int sg  = (c & 3) << 4;
        uint32_t soff = (uint32_t)row * (KPAD * 2) + (uint32_t)sg;
        size_t   goff = (size_t)row * (DM * 2) + sg;
        asm volatile("cp.async.cg.shared.global [%0], [%1], 16;"
                     :: "r"(st + 0 * TILE_B + soff), "l"((const char*)ah + goff) : "memory");
        asm volatile("cp.async.cg.shared.global [%0], [%1], 16;"
                     :: "r"(st + 1 * TILE_B + soff), "l"((const char*)al + goff) : "memory");
        asm volatile("cp.async.cg.shared.global [%0], [%1], 16;"
                     :: "r"(st + 2 * TILE_B + soff), "l"((const char*)bh + goff) : "memory");
        asm volatile("cp.async.cg.shared.global [%0], [%1], 16;"
                     :: "r"(st + 3 * TILE_B + soff), "l"((const char*)bl + goff) : "memory");
    }
}

__global__ void __launch_bounds__(256)
gemm_tc(const __nv_bfloat16* __restrict__ Ah, const __nv_bfloat16* __restrict__ Al,
        const __nv_bfloat16* __restrict__ B0h, const __nv_bfloat16* __restrict__ B0l,
        const __nv_bfloat16* __restrict__ B1h, const __nv_bfloat16* __restrict__ B1l,
        const __nv_bfloat16* __restrict__ B2h, const __nv_bfloat16* __restrict__ B2l,
        float* __restrict__ Dout,
        __nv_bfloat16* __restrict__ Oqh, __nv_bfloat16* __restrict__ Oql,
        __nv_bfloat16* __restrict__ Okh, __nv_bfloat16* __restrict__ Okl,
        __nv_bfloat16* __restrict__ Ovh, __nv_bfloat16* __restrict__ Ovl,
        int mode) {
    extern __shared__ char smraw[];
    const uint32_t sb = s2u(smraw);

    const int tid  = threadIdx.x;
    const int lane = tid & 31;
    const int wid  = tid >> 5;
    const int warp_m = (wid & 1) * 64;
    const int warp_n = (wid >> 1) * 32;

    const int ntile = blockIdx.x;
    const int which = ntile >> 3;
    const int nloc  = (ntile & 7) * 128;
    const int m0    = blockIdx.y * 128;

    const __nv_bfloat16* Bh = (which == 0) ? B0h : (which == 1) ? B1h : B2h;
    const __nv_bfloat16* Bl = (which == 0) ? B0l : (which == 1) ? B1l : B2l;

    const __nv_bfloat16* Abh = Ah + (size_t)m0 * DM;
    const __nv_bfloat16* Abl = Al + (size_t)m0 * DM;
    const __nv_bfloat16* Bbh = Bh + (size_t)nloc * DM;
    const __nv_bfloat16* Bbl = Bl + (size_t)nloc * DM;

    float acc[4][4][4];
    #pragma unroll
    for (int i = 0; i < 4; i++)
        #pragma unroll
        for (int j = 0; j < 4; j++)
            #pragma unroll
            for (int r = 0; r < 4; r++) acc[i][j][r] = 0.0f;

    const uint32_t a_off = (uint32_t)(lane & 15) * (KPAD * 2) + (uint32_t)(lane >> 4) * 16;
    const int bl16 = lane & 15;
    const uint32_t b_off = (uint32_t)(bl16 & 7) * (KPAD * 2) + (uint32_t)(bl16 >> 3) * 16;

    load_tile4(sb, Abh, Abl, Bbh, Bbl, tid);
    asm volatile("cp.async.commit_group;" ::: "memory");

    for (int kb = 0; kb < 32; kb++) {
        const uint32_t st = sb + (uint32_t)(kb & 1) * STAGE_B;
        if (kb + 1 < 32) {
            const int ko = (kb + 1) * 32;
            load_tile4(sb + (uint32_t)((kb + 1) & 1) * STAGE_B,
                       Abh + ko, Abl + ko, Bbh + ko, Bbl + ko, tid);
            asm volatile("cp.async.commit_group;" ::: "memory");
            asm volatile("cp.async.wait_group 1;" ::: "memory");
        } else {
            asm volatile("cp.async.wait_group 0;" ::: "memory");
        }
        __syncthreads();

        #pragma unroll
        for (int ks = 0; ks < 2; ks++) {
            const uint32_t k0b = (uint32_t)ks * 32;
            uint32_t ahf[4][4], alf[4][4], bhf[4][2], blf[4][2];
            #pragma unroll
            for (int mi = 0; mi < 4; mi++) {
                uint32_t ra = (uint32_t)(warp_m + mi * 16) * (KPAD * 2) + k0b + a_off;
                ldsm4(ahf[mi], st + 0 * TILE_B + ra);
                ldsm4(alf[mi], st + 1 * TILE_B + ra);
            }
            #pragma unroll
            for (int ni = 0; ni < 4; ni++) {
                uint32_t rb = (uint32_t)(warp_n + ni * 8) * (KPAD * 2) + k0b + b_off;
                ldsm2(bhf[ni], st + 2 * TILE_B + rb);
                ldsm2(blf[ni], st + 3 * TILE_B + rb);
            }
            #pragma unroll
            for (int mi = 0; mi < 4; mi++)
                #pragma unroll
                for (int ni = 0; ni < 4; ni++) {
                    mma16816(acc[mi][ni], ahf[mi], bhf[ni]);
                    mma16816(acc[mi][ni], ahf[mi], blf[ni]);
                    mma16816(acc[mi][ni], alf[mi], bhf[ni]);
                }
        }
        __syncthreads();
    }

    const int rope = (mode == 1) && (which < 2);
    __nv_bfloat16* Wh = (which == 0) ? Oqh : (which == 1) ? Okh : Ovh;
    __nv_bfloat16* Wl = (which == 0) ? Oql : (which == 1) ? Okl : Ovl;

    #pragma unroll
    for (int mi = 0; mi < 4; mi++) {
        #pragma unroll
        for (int ni = 0; ni < 4; ni++) {
            const int r0  = m0 + warp_m + mi * 16 + (lane >> 2);
            const int col = nloc + warp_n + ni * 8 + (lane & 3) * 2;
            float c0 = acc[mi][ni][0], c1 = acc[mi][ni][1];
            float c2 = acc[mi][ni][2], c3 = acc[mi][ni][3];
            if (rope) {
                const int jj = (col & (DK - 1)) >> 1;
                float cs = g_rope_cos[r0 * 32 + jj];
                float sn = g_rope_sin[r0 * 32 + jj];
                float e = c0, o = c1;
                c0 = cs * e - sn * o;
                c1 = sn * e + cs * o;
                cs = g_rope_cos[(r0 + 8) * 32 + jj];
                sn = g_rope_sin[(r0 + 8) * 32 + jj];
                e = c2; o = c3;
                c2 = cs * e - sn * o;
                c3 = sn * e + cs * o;
            }
            if (mode == 0) {
                *(float2*)&Dout[(size_t)r0 * DM + col]       = make_float2(c0, c1);
                *(float2*)&Dout[(size_t)(r0 + 8) * DM + col] = make_float2(c2, c3);
            } else {
                const int head = col >> 6;
                const int d    = col & 63;
                const size_t p0 = ((size_t)head * SEQ + r0) * DK + d;
                const size_t p1 = ((size_t)head * SEQ + r0 + 8) * DK + d;
                __nv_bfloat162 h0 = __float22bfloat162_rn(make_float2(c0, c1));
                __nv_bfloat162 h1 = __float22bfloat162_rn(make_float2(c2, c3));
                __nv_bfloat162 l0 = __float22bfloat162_rn(make_float2(
                    c0 - __low2float(h0), c1 - __high2float(h0)));
                __nv_bfloat162 l1 = __float22bfloat162_rn(make_float2(
                    c2 - __low2float(h1), c3 - __high2float(h1)));
                *(__nv_bfloat162*)&Wh[p0] = h0;
                *(__nv_bfloat162*)&Wh[p1] = h1;
                *(__nv_bfloat162*)&Wl[p0] = l0;
                *(__nv_bfloat162*)&Wl[p1] = l1;
            }
        }
    }
}

// ============================================================
// Tensor-core causal flash attention.
// CTA = (head, 64-query block). 128 thr, 4 warps x 16 rows.
// K blocks of 64 keys; bf16x3 split for both S=QK^T and O=PV.
// ============================================================
#define ASTR  72                       // halves per smem row
#define ATILE (64 * ASTR * 2)          // 9216 B per 64x64 tile
#define ATT_SMEM (10 * ATILE)          // Qh,Ql + 2 stages x (Kh,Kl,Vh,Vl)

__device__ __forceinline__ void aload(uint32_t dst, const __nv_bfloat16* src,
                                      int tid) {
    const char* s = (const char*)src;
    #pragma unroll
    for (int i = 0; i < 4; i++) {
        int c   = tid + 128 * i;
        int row = c >> 3;
        int seg = (c & 7) << 4;
        asm volatile("cp.async.cg.shared.global [%0], [%1], 16;"
                     :: "r"(dst + (uint32_t)row * (ASTR * 2) + (uint32_t)seg),
                        "l"(s + (size_t)row * 128 + seg) : "memory");
    }
}

__global__ void __launch_bounds__(128) attn_tc() {
    extern __shared__ char smraw[];
    const uint32_t sb   = s2u(smraw);
    const uint32_t qh_s = sb;
    const uint32_t ql_s = sb + ATILE;
    const uint32_t kv0  = sb + 2 * ATILE;   // + stage*4*ATILE: Kh,Kl,Vh,Vl

    const int tid  = threadIdx.x;
    const int lane = tid & 31;
    const int warp = tid >> 5;
    const int h    = blockIdx.y;
    const int qb   = gridDim.x - 1 - blockIdx.x;   // heavy-first
    const int q0   = qb * 64;

    const size_t hb = (size_t)h * SEQ * DK;

    // Q tile + KV block 0
    aload(qh_s, g_qh + hb + (size_t)q0 * DK, tid);
    aload(ql_s, g_ql + hb + (size_t)q0 * DK, tid);
    aload(kv0 + 0 * ATILE, g_kh + hb, tid);
    aload(kv0 + 1 * ATILE, g_kl + hb, tid);
    aload(kv0 + 2 * ATILE, g_vh + hb, tid);
    aload(kv0 + 3 * ATILE, g_vl + hb, tid);
    asm volatile("cp.async.commit_group;" ::: "memory");

    float o[8][4];
    #pragma unroll
    for (int j = 0; j < 8; j++)
        #pragma unroll
        for (int c = 0; c < 4; c++) o[j][c] = 0.0f;
    float m0 = -1e30f, m1 = -1e30f, l0 = 0.0f, l1 = 0.0f;

    // precomputed intra-tile offsets (bytes)
    const uint32_t qoff = (uint32_t)(warp * 16 + (lane & 15)) * (ASTR * 2)
                        + (uint32_t)(lane >> 4) * 16;
    const uint32_t krow = (uint32_t)((lane & 7) + ((lane >> 4) & 1) * 8);
    const uint32_t kcol = (uint32_t)((lane >> 3) & 1) * 16;
    const uint32_t vrow = (uint32_t)((lane & 7) + ((lane >> 3) & 1) * 8);
    const uint32_t vcol = (uint32_t)(lane >> 4) * 16;
    const float L2E = 1.44269504f;

    for (int kb = 0; kb <= qb; kb++) {
        if (kb < qb) {
            const uint32_t nst = kv0 + (uint32_t)((kb + 1) & 1) * (4 * ATILE);
            const size_t   gof = hb + (size_t)(kb + 1) * 64 * DK;
            aload(nst + 0 * ATILE, g_kh + gof, tid);
            aload(nst + 1 * ATILE, g_kl + gof, tid);
            aload(nst + 2 * ATILE, g_vh + gof, tid);
            aload(nst + 3 * ATILE, g_vl + gof, tid);
            asm volatile("cp.async.commit_group;" ::: "memory");
            asm volatile("cp.async.wait_group 1;" ::: "memory");
        } else {
            asm volatile("cp.async.wait_group 0;" ::: "memory");
        }
        __syncthreads();

        const uint32_t st  = kv0 + (uint32_t)(kb & 1) * (4 * ATILE);
        const uint32_t kh_s = st, kl_s = st + ATILE;
        const uint32_t vh_s = st + 2 * ATILE, vl_s = st + 3 * ATILE;

        // ---- S = Q K^T (bf16x3) ----
        float sc[8][4];
        #pragma unroll
        for (int j = 0; j < 8; j++)
            #pragma unroll
            for (int c = 0; c < 4; c++) sc[j][c] = 0.0f;

        #pragma unroll
        for (int ks = 0; ks < 4; ks++) {
            uint32_t aqh[4], aql[4];
            ldsm4(aqh, qh_s + qoff + ks * 32);
            ldsm4(aql, ql_s + qoff + ks * 32);
            #pragma unroll
            for (int nb = 0; nb < 4; nb++) {
                uint32_t ra = (uint32_t)(nb * 16 + krow) * (ASTR * 2) + kcol + ks * 32;
                uint32_t bkh[4], bkl[4];
                ldsm4(bkh, kh_s + ra);
                ldsm4(bkl, kl_s + ra);
                mma16816(sc[2 * nb],     aqh, &bkh[0]);
                mma16816(sc[2 * nb],     aqh, &bkl[0]);
                mma16816(sc[2 * nb],     aql, &bkh[0]);
                mma16816(sc[2 * nb + 1], aqh, &bkh[2]);
                mma16816(sc[2 * nb + 1], aqh, &bkl[2]);
                mma16816(sc[2 * nb + 1], aql, &bkh[2]);
            }
        }

        // ---- scale + causal mask ----
        #pragma unroll
        for (int j = 0; j < 8; j++)
            #pragma unroll
            for (int c = 0; c < 4; c++) sc[j][c] *= 0.125f;
        if (kb == qb) {
            const int r0 = q0 + warp * 16 + (lane >> 2);
            #pragma unroll
            for (int j = 0; j < 8; j++)
                #pragma unroll
                for (int c = 0; c < 4; c++) {
                    const int col = kb * 64 + j * 8 + (lane & 3) * 2 + (c & 1);
                    const int row = r0 + (c >> 1) * 8;
                    if (col > row) sc[j][c] = -1e30f;
                }
        }

        // ---- online softmax ----
        float mx0 = -1e30f, mx1 = -1e30f;
        #pragma unroll
        for (int j = 0; j < 8; j++) {
            mx0 = fmaxf(mx0, fmaxf(sc[j][0], sc[j][1]));
            mx1 = fmaxf(mx1, fmaxf(sc[j][2], sc[j][3]));
        }
        mx0 = fmaxf(mx0, __shfl_xor_sync(0xffffffffu, mx0, 1));
        mx0 = fmaxf(mx0, __shfl_xor_sync(0xffffffffu, mx0, 2));
        mx1 = fmaxf(mx1, __shfl_xor_sync(0xffffffffu, mx1, 1));
        mx1 = fmaxf(mx1, __shfl_xor_sync(0xffffffffu, mx1, 2));
        const float mn0 = fmaxf(m0, mx0), mn1 = fmaxf(m1, mx1);
        const float a0  = exp2f((m0 - mn0) * L2E);
        const float a1  = exp2f((m1 - mn1) * L2E);
        m0 = mn0; m1 = mn1;

        float s0 = 0.0f, s1 = 0.0f;
        #pragma unroll
        for (int j = 0; j < 8; j++) {
            sc[j][0] = exp2f((sc[j][0] - mn0) * L2E);
            sc[j][1] = exp2f((sc[j][1] - mn0) * L2E);
            sc[j][2] = exp2f((sc[j][2] - mn1) * L2E);
            sc[j][3] = exp2f((sc[j][3] - mn1) * L2E);
            s0 += sc[j][0] + sc[j][1];
            s1 += sc[j][2] + sc[j][3];
        }
        s0 += __shfl_xor_sync(0xffffffffu, s0, 1);
        s0 += __shfl_xor_sync(0xffffffffu, s0, 2);
        s1 += __shfl_xor_sync(0xffffffffu, s1, 1);
        s1 += __shfl_xor_sync(0xffffffffu, s1, 2);
        l0 = l0 * a0 + s0;
        l1 = l1 * a1 + s1;
        #pragma unroll
        for (int j = 0; j < 8; j++) {
            o[j][0] *= a0; o[j][1] *= a0;
            o[j][2] *= a1; o[j][3] *= a1;
        }

        // ---- O += P V (bf16x3, P repacked C->A in registers) ----
        #pragma unroll
        for (int j = 0; j < 4; j++) {
            const int t0 = 2 * j, t1 = 2 * j + 1;
            uint32_t ph[4], pl[4];
            ph[0] = packbf2(sc[t0][0], sc[t0][1]);
            ph[1] = packbf2(sc[t0][2], sc[t0][3]);
            ph[2] = packbf2(sc[t1][0], sc[t1][1]);
            ph[3] = packbf2(sc[t1][2], sc[t1][3]);
            {
                __nv_bfloat162 b0 = *(__nv_bfloat162*)&ph[0];
                __nv_bfloat162 b1 = *(__nv_bfloat162*)&ph[1];
                __nv_bfloat162 b2 = *(__nv_bfloat162*)&ph[2];
                __nv_bfloat162 b3 = *(__nv_bfloat162*)&ph[3];
                pl[0] = packbf2(sc[t0][0] - __low2float(b0), sc[t0][1] - __high2float(b0));
                pl[1] = packbf2(sc[t0][2] - __low2float(b1), sc[t0][3] - __high2float(b1));
                pl[2] = packbf2(sc[t1][0] - __low2float(b2), sc[t1][1] - __high2float(b2));
                pl[3] = packbf2(sc[t1][2] - __low2float(b3), sc[t1][3] - __high2float(b3));
            }
            #pragma unroll
            for (int nb = 0; nb < 4; nb++) {
                uint32_t ra = (uint32_t)(j * 16 + vrow) * (ASTR * 2) + vcol + nb * 32;
                uint32_t bvh[4], bvl[4];
                ldsm4t(bvh, vh_s + ra);
                ldsm4t(bvl, vl_s + ra);
                mma16816(o[2 * nb],     ph, &bvh[0]);
                mma16816(o[2 * nb],     ph, &bvl[0]);
                mma16816(o[2 * nb],     pl, &bvh[0]);
                mma16816(o[2 * nb + 1], ph, &bvh[2]);
                mma16816(o[2 * nb + 1], ph, &bvl[2]);
                mma16816(o[2 * nb + 1], pl, &bvh[2]);
            }
        }
        __syncthreads();
    }

    // ---- normalize + write bf16 hi/lo (row-major [SEQ][DM]) ----
    const float inv0 = 1.0f / l0, inv1 = 1.0f / l1;
    const int r  = q0 + warp * 16 + (lane >> 2);
    const int cb = h * 64 + (lane & 3) * 2;
    #pragma unroll
    for (int j = 0; j < 8; j++) {
        const int col = cb + j * 8;
        float f0 = o[j][0] * inv0, f1 = o[j][1] * inv0;
        float f2 = o[j][2] * inv1, f3 = o[j][3] * inv1;
        __nv_bfloat162 h0 = __float22bfloat162_rn(make_float2(f0, f1));
        __nv_bfloat162 h1 = __float22bfloat162_rn(make_float2(f2, f3));
        __nv_bfloat162 l0v = __float22bfloat162_rn(make_float2(
            f0 - __low2float(h0), f1 - __high2float(h0)));
        __nv_bfloat162 l1v = __float22bfloat162_rn(make_float2(
            f2 - __low2float(h1), f3 - __high2float(h1)));
        *(__nv_bfloat162*)&g_ah[(size_t)r * DM + col]       = h0;
        *(__nv_bfloat162*)&g_al[(size_t)r * DM + col]       = l0v;
        *(__nv_bfloat162*)&g_ah[(size_t)(r + 8) * DM + col] = h1;
        *(__nv_bfloat162*)&g_al[(size_t)(r + 8) * DM + col] = l1v;
    }
}

// ============================================================
// launch
// ============================================================
extern "C" void kernel_launch(void* const* d_in, const int* in_sizes, int n_in,
                              void* d_out, int out_size) {
    const float* x  = (const float*)d_in[0];
    const float* wq = (const float*)d_in[1];
    const float* wk = (const float*)d_in[2];
    const float* wv = (const float*)d_in[3];
    const float* wo = (const float*)d_in[4];
    float* out = (float*)d_out;

    __nv_bfloat16 *xh, *xl, *ah, *al;
    __nv_bfloat16 *wqh, *wql, *wkh, *wkl, *wvh, *wvl, *woh, *wol;
    __nv_bfloat16 *qh, *ql, *kh, *kl, *vh, *vl;
    cudaGetSymbolAddress((void**)&xh,  g_xh);
    cudaGetSymbolAddress((void**)&xl,  g_xl);
    cudaGetSymbolAddress((void**)&ah,  g_ah);
    cudaGetSymbolAddress((void**)&al,  g_al);
    cudaGetSymbolAddress((void**)&wqh, g_wqh);
    cudaGetSymbolAddress((void**)&wql, g_wql);
    cudaGetSymbolAddress((void**)&wkh, g_wkh);
    cudaGetSymbolAddress((void**)&wkl, g_wkl);
    cudaGetSymbolAddress((void**)&wvh, g_wvh);
    cudaGetSymbolAddress((void**)&wvl, g_wvl);
    cudaGetSymbolAddress((void**)&woh, g_woh);
    cudaGetSymbolAddress((void**)&wol, g_wol);
    cudaGetSymbolAddress((void**)&qh,  g_qh);
    cudaGetSymbolAddress((void**)&ql,  g_ql);
    cudaGetSymbolAddress((void**)&kh,  g_kh);
    cudaGetSymbolAddress((void**)&kl,  g_kl);
    cudaGetSymbolAddress((void**)&vh,  g_vh);
    cudaGetSymbolAddress((void**)&vl,  g_vl);

    cudaFuncSetAttribute(gemm_tc,
                         cudaFuncAttributeMaxDynamicSharedMemorySize, GEMM_SMEM);
    cudaFuncSetAttribute(attn_tc,
                         cudaFuncAttributeMaxDynamicSharedMemorySize, ATT_SMEM);

    rope_table_kernel<<<(SEQ * 32) / 256, 256>>>();

    const int nx4 = SEQ * DM / 4;
    const int nw4 = DM * DM / 4;
    conv_split<<<(nx4 + 255) / 256, 256>>>((const float4*)x,
                                           (__nv_bfloat162*)xh, (__nv_bfloat162*)xl, nx4);
    conv_split<<<(nw4 + 255) / 256, 256>>>((const float4*)wq,
                                           (__nv_bfloat162*)wqh, (__nv_bfloat162*)wql, nw4);
    conv_split<<<(nw4 + 255) / 256, 256>>>((const float4*)wk,
                                           (__nv_bfloat162*)wkh, (__nv_bfloat162*)wkl, nw4);
    conv_split<<<(nw4 + 255) / 256, 256>>>((const float4*)wv,
                                           (__nv_bfloat162*)wvh, (__nv_bfloat162*)wvl, nw4);
    conv_split<<<(nw4 + 255) / 256, 256>>>((const float4*)wo,
                                           (__nv_bfloat162*)woh, (__nv_bfloat162*)wol, nw4);

    // QKV: 24 N-tiles -> bf16 hi/lo head-major with fused RoPE
    gemm_tc<<<dim3(24, 32), 256, GEMM_SMEM>>>(xh, xl,
                                              wqh, wql, wkh, wkl, wvh, wvl,
                                              nullptr,
                                              qh, ql, kh, kl, vh, vl, 1);

    attn_tc<<<dim3(SEQ / 64, NH), 128, ATT_SMEM>>>();

    // Wo: fp32 out
    gemm_tc<<<dim3(8, 32), 256, GEMM_SMEM>>>(ah, al,
                                             woh, wol, woh, wol, woh, wol,
                                             out,
                                             nullptr, nullptr, nullptr,
                                             nullptr, nullptr, nullptr, 0);
}